// round 5
// baseline (speedup 1.0000x reference)
#include <cuda_runtime.h>
#include <cuda_bf16.h>
#include <cstdint>

// Problem constants
#define BB   16
#define NN   2048
#define TT   168
#define DD   64
#define MM   2216            // N + T
#define TM   128
#define NT   18              // ceil(MM/128)
#define PAIRS 171            // NT*(NT+1)/2

// SMEM regions (bf16 [128][64] tiles, 128B rows, SW128-swizzled), 16KB each.
// After MMA, whole region is reused as Cs: float [128 cols][pitch 132].
#define AHI_OFF 0
#define ALO_OFF 16384
#define BHI_OFF 32768
#define BLO_OFF 49152
#define CS_PITCH 132
#define SMEM_BYTES (128*CS_PITCH*4)   // 67584 >= 65536

__device__ __forceinline__ uint32_t smem_u32(const void* p) {
    uint32_t a;
    asm("{ .reg .u64 t; cvta.to.shared.u64 t, %1; cvt.u32.u64 %0, t; }" : "=r"(a) : "l"(p));
    return a;
}

__device__ __forceinline__ float tanh_relu(float x) {
    x = fmaxf(x, 0.0f);
    float y;
    asm("tanh.approx.f32 %0, %1;" : "=f"(y) : "f"(x));
    return y;
}

__device__ __forceinline__ uint32_t sw128(uint32_t off) {
    return off ^ ((off >> 3) & 0x70);
}

// convert 8 floats (v0,v1) -> 16B hi + 16B lo bf16 packs
__device__ __forceinline__ void split8(float4 v0, float4 v1, uint4& hp, uint4& lp) {
    __nv_bfloat162 h01 = __floats2bfloat162_rn(v0.x, v0.y);
    __nv_bfloat162 h23 = __floats2bfloat162_rn(v0.z, v0.w);
    __nv_bfloat162 h45 = __floats2bfloat162_rn(v1.x, v1.y);
    __nv_bfloat162 h67 = __floats2bfloat162_rn(v1.z, v1.w);
    __nv_bfloat162 l01 = __floats2bfloat162_rn(
        v0.x - __bfloat162float(__low2bfloat16(h01)),
        v0.y - __bfloat162float(__high2bfloat16(h01)));
    __nv_bfloat162 l23 = __floats2bfloat162_rn(
        v0.z - __bfloat162float(__low2bfloat16(h23)),
        v0.w - __bfloat162float(__high2bfloat16(h23)));
    __nv_bfloat162 l45 = __floats2bfloat162_rn(
        v1.x - __bfloat162float(__low2bfloat16(h45)),
        v1.y - __bfloat162float(__high2bfloat16(h45)));
    __nv_bfloat162 l67 = __floats2bfloat162_rn(
        v1.z - __bfloat162float(__low2bfloat16(h67)),
        v1.w - __bfloat162float(__high2bfloat16(h67)));
    hp.x = *(uint32_t*)&h01; hp.y = *(uint32_t*)&h23;
    hp.z = *(uint32_t*)&h45; hp.w = *(uint32_t*)&h67;
    lp.x = *(uint32_t*)&l01; lp.y = *(uint32_t*)&l23;
    lp.z = *(uint32_t*)&l45; lp.w = *(uint32_t*)&l67;
}

__device__ __forceinline__ void ldsm_x4(uint32_t addr, uint32_t& r0, uint32_t& r1,
                                        uint32_t& r2, uint32_t& r3) {
    asm volatile("ldmatrix.sync.aligned.m8n8.x4.shared.b16 {%0,%1,%2,%3}, [%4];"
                 : "=r"(r0), "=r"(r1), "=r"(r2), "=r"(r3) : "r"(addr));
}

__device__ __forceinline__ void mma16816(float* c, const uint32_t* a, const uint32_t* b) {
    asm volatile(
        "mma.sync.aligned.m16n8k16.row.col.f32.bf16.bf16.f32 "
        "{%0,%1,%2,%3}, {%4,%5,%6,%7}, {%8,%9}, {%0,%1,%2,%3};"
        : "+f"(c[0]), "+f"(c[1]), "+f"(c[2]), "+f"(c[3])
        : "r"(a[0]), "r"(a[1]), "r"(a[2]), "r"(a[3]), "r"(b[0]), "r"(b[1]));
}

__global__ __launch_bounds__(256, 2)
void stg_sym2_kernel(const float* __restrict__ sp, const float* __restrict__ tp,
                     float* __restrict__ out)
{
    extern __shared__ char smem[];
    const uint32_t smem_base = smem_u32(smem);

    const int t    = threadIdx.x;
    const int lane = t & 31;
    const int wid  = t >> 5;

    const int b = blockIdx.y;
    int p = blockIdx.x;
    int ti = 0;
    while (p >= NT - ti) { p -= NT - ti; ++ti; }
    const int tj = ti + p;                 // ti <= tj
    const int row0 = ti * TM;
    const int col0 = tj * TM;
    const bool diag = (ti == tj);

    // ---- load + split-convert A tile; off-diag also B tile ----
    // thread handles 8 consecutive floats: 128 rows * 8 groups = 1024 units -> 4 iters
    #pragma unroll
    for (int i = 0; i < 4; ++i) {
        int idx = i * 256 + t;
        int r   = idx >> 3;
        int c8  = idx & 7;
        int g   = row0 + r;
        float4 v0 = make_float4(0.f,0.f,0.f,0.f), v1 = v0;
        if (g < MM) {
            const float* ptr = (g < NN) ? sp + ((size_t)b * NN + g) * DD
                                        : tp + ((size_t)b * TT + (g - NN)) * DD;
            v0 = ((const float4*)ptr)[c8 * 2];
            v1 = ((const float4*)ptr)[c8 * 2 + 1];
        }
        uint4 hp, lp;
        split8(v0, v1, hp, lp);
        uint32_t sw = sw128((uint32_t)r * 128 + (uint32_t)c8 * 16);
        *(uint4*)(smem + AHI_OFF + sw) = hp;
        *(uint4*)(smem + ALO_OFF + sw) = lp;
    }
    if (!diag) {
        #pragma unroll
        for (int i = 0; i < 4; ++i) {
            int idx = i * 256 + t;
            int r   = idx >> 3;
            int c8  = idx & 7;
            int g   = col0 + r;
            float4 v0 = make_float4(0.f,0.f,0.f,0.f), v1 = v0;
            if (g < MM) {
                const float* ptr = (g < NN) ? sp + ((size_t)b * NN + g) * DD
                                            : tp + ((size_t)b * TT + (g - NN)) * DD;
                v0 = ((const float4*)ptr)[c8 * 2];
                v1 = ((const float4*)ptr)[c8 * 2 + 1];
            }
            uint4 hp, lp;
            split8(v0, v1, hp, lp);
            uint32_t sw = sw128((uint32_t)r * 128 + (uint32_t)c8 * 16);
            *(uint4*)(smem + BHI_OFF + sw) = hp;
            *(uint4*)(smem + BLO_OFF + sw) = lp;
        }
    }
    __syncthreads();

    // ---- warp tiles: 4 (m) x 2 (n) warps, each 32x64 ----
    const int m0w = (wid & 3) * 32;
    const int n0w = (wid >> 2) * 64;

    float acc[2][8][4];
    #pragma unroll
    for (int mi = 0; mi < 2; ++mi)
        #pragma unroll
        for (int ni = 0; ni < 8; ++ni)
            #pragma unroll
            for (int q = 0; q < 4; ++q) acc[mi][ni][q] = 0.0f;

    const int a_row  = m0w + (lane & 15);
    const int a_chk  = lane >> 4;
    const int b_rowb = n0w + ((lane >> 4) << 3) + (lane & 7);
    const int b_chk  = (lane >> 3) & 1;

    const uint32_t ahibase = smem_base + AHI_OFF;
    const uint32_t alobase = smem_base + ALO_OFF;
    const uint32_t bhibase = smem_base + (diag ? AHI_OFF : BHI_OFF);
    const uint32_t blobase = smem_base + (diag ? ALO_OFF : BLO_OFF);

    // kc-outer: per k-chunk load frags once, run all three passes
    #pragma unroll
    for (int kk = 0; kk < 4; ++kk) {
        const int kc = kk * 2;
        uint32_t a_off[2], b_off[4];
        #pragma unroll
        for (int mi = 0; mi < 2; ++mi)
            a_off[mi] = sw128((uint32_t)(a_row + mi * 16) * 128 + (uint32_t)(kc + a_chk) * 16);
        #pragma unroll
        for (int bi = 0; bi < 4; ++bi)
            b_off[bi] = sw128((uint32_t)(b_rowb + bi * 16) * 128 + (uint32_t)(kc + b_chk) * 16);

        uint32_t af[2][4], bfh[8][2], bfl[8][2];
        // B hi
        #pragma unroll
        for (int bi = 0; bi < 4; ++bi)
            ldsm_x4(bhibase + b_off[bi], bfh[2*bi][0], bfh[2*bi][1], bfh[2*bi+1][0], bfh[2*bi+1][1]);
        // A hi
        #pragma unroll
        for (int mi = 0; mi < 2; ++mi)
            ldsm_x4(ahibase + a_off[mi], af[mi][0], af[mi][1], af[mi][2], af[mi][3]);
        // Ahi * Bhi
        #pragma unroll
        for (int mi = 0; mi < 2; ++mi)
            #pragma unroll
            for (int ni = 0; ni < 8; ++ni)
                mma16816(acc[mi][ni], af[mi], bfh[ni]);
        // B lo
        #pragma unroll
        for (int bi = 0; bi < 4; ++bi)
            ldsm_x4(blobase + b_off[bi], bfl[2*bi][0], bfl[2*bi][1], bfl[2*bi+1][0], bfl[2*bi+1][1]);
        // Ahi * Blo
        #pragma unroll
        for (int mi = 0; mi < 2; ++mi)
            #pragma unroll
            for (int ni = 0; ni < 8; ++ni)
                mma16816(acc[mi][ni], af[mi], bfl[ni]);
        // A lo (overwrite af)
        #pragma unroll
        for (int mi = 0; mi < 2; ++mi)
            ldsm_x4(alobase + a_off[mi], af[mi][0], af[mi][1], af[mi][2], af[mi][3]);
        // Alo * Bhi
        #pragma unroll
        for (int mi = 0; mi < 2; ++mi)
            #pragma unroll
            for (int ni = 0; ni < 8; ++ni)
                mma16816(acc[mi][ni], af[mi], bfh[ni]);
    }

    // ---- activation in place ----
    #pragma unroll
    for (int mi = 0; mi < 2; ++mi)
        #pragma unroll
        for (int ni = 0; ni < 8; ++ni)
            #pragma unroll
            for (int q = 0; q < 4; ++q)
                acc[mi][ni][q] = tanh_relu(acc[mi][ni][q]);

    // ---- direct write: out[row0+r][col0+c], coalesced float2 ----
    #pragma unroll
    for (int mi = 0; mi < 2; ++mi) {
        #pragma unroll
        for (int rh = 0; rh < 2; ++rh) {
            const int gr = row0 + m0w + mi * 16 + rh * 8 + (lane >> 2);
            if (gr >= MM) continue;
            const size_t rbase = ((size_t)b * MM + gr) * MM;
            #pragma unroll
            for (int ni = 0; ni < 8; ++ni) {
                const int gc = col0 + n0w + ni * 8 + (lane & 3) * 2;
                if (gc < MM) {
                    float2 v;
                    v.x = acc[mi][ni][rh * 2];
                    v.y = acc[mi][ni][rh * 2 + 1];
                    *(float2*)&out[rbase + gc] = v;
                }
            }
        }
    }

    // ---- mirror write via SMEM transpose (off-diagonal only) ----
    if (!diag) {
        __syncthreads();                   // done reading A/B tiles
        float* Cs = (float*)smem;          // [c:128][r: pitch 132]
        #pragma unroll
        for (int mi = 0; mi < 2; ++mi) {
            #pragma unroll
            for (int rh = 0; rh < 2; ++rh) {
                const int r = m0w + mi * 16 + rh * 8 + (lane >> 2);
                #pragma unroll
                for (int ni = 0; ni < 8; ++ni) {
                    const int c = n0w + ni * 8 + (lane & 3) * 2;
                    Cs[(c)     * CS_PITCH + r] = acc[mi][ni][rh * 2];
                    Cs[(c + 1) * CS_PITCH + r] = acc[mi][ni][rh * 2 + 1];
                }
            }
        }
        __syncthreads();
        // read rows of Cs (f4, conflict-free), write out[col0+c][row0+r] coalesced
        #pragma unroll
        for (int i = 0; i < 16; ++i) {
            int u   = i * 256 + t;         // 4096 f4 total
            int lr4 = u & 31;
            int lc  = u >> 5;
            float4 v = *(const float4*)&Cs[lc * CS_PITCH + 4 * lr4];
            int gr_out = col0 + lc;        // output row (in tj tile)
            int gc_out = row0 + 4 * lr4;   // output cols (in ti tile), MM%4==0
            if (gr_out < MM && gc_out < MM) {
                *(float4*)&out[((size_t)b * MM + gr_out) * MM + gc_out] = v;
            }
        }
    }
}

extern "C" void kernel_launch(void* const* d_in, const int* in_sizes, int n_in,
                              void* d_out, int out_size)
{
    const float* sp = (const float*)d_in[0];   // spatial  [16,2048,64] f32
    const float* tp = (const float*)d_in[1];   // temporal [16, 168,64] f32
    float* out = (float*)d_out;                // [16,2216,2216] f32

    cudaFuncSetAttribute(stg_sym2_kernel, cudaFuncAttributeMaxDynamicSharedMemorySize, SMEM_BYTES);
    dim3 grid(PAIRS, BB);
    stg_sym2_kernel<<<grid, 256, SMEM_BYTES>>>(sp, tp, out);
}

// round 6
// speedup vs baseline: 1.0672x; 1.0672x over previous
#include <cuda_runtime.h>
#include <cuda_bf16.h>
#include <cstdint>

// Problem constants
#define BB   16
#define NN   2048
#define TT   168
#define DD   64
#define MM   2216            // N + T
#define TMR  64              // tile rows (A strip)
#define TNC  128             // tile cols (B strip)
#define NTI  35              // ceil(MM/64)
#define NTJ  18              // ceil(MM/128)
#define TILES_PER_B 341      // sum over i of (18 - floor(i/2))

// SMEM: bf16 tiles, 128B rows, SW128-swizzled.
// A: 64 rows hi+lo = 8KB+8KB ; B: 128 rows hi+lo = 16KB+16KB. Total 48KB.
// After MMA, reused as Cs float[c:128][r: pitch 68] = 34.8KB.
#define AHI_OFF 0
#define ALO_OFF 8192
#define BHI_OFF 16384
#define BLO_OFF 32768
#define CS_PITCH 68
#define SMEM_BYTES 49152

__device__ __forceinline__ uint32_t smem_u32(const void* p) {
    uint32_t a;
    asm("{ .reg .u64 t; cvta.to.shared.u64 t, %1; cvt.u32.u64 %0, t; }" : "=r"(a) : "l"(p));
    return a;
}

__device__ __forceinline__ float tanh_relu(float x) {
    x = fmaxf(x, 0.0f);
    float y;
    asm("tanh.approx.f32 %0, %1;" : "=f"(y) : "f"(x));
    return y;
}

__device__ __forceinline__ uint32_t sw128(uint32_t off) {
    return off ^ ((off >> 3) & 0x70);
}

// convert 8 floats -> 16B hi + 16B lo bf16 packs
__device__ __forceinline__ void split8(float4 v0, float4 v1, uint4& hp, uint4& lp) {
    __nv_bfloat162 h01 = __floats2bfloat162_rn(v0.x, v0.y);
    __nv_bfloat162 h23 = __floats2bfloat162_rn(v0.z, v0.w);
    __nv_bfloat162 h45 = __floats2bfloat162_rn(v1.x, v1.y);
    __nv_bfloat162 h67 = __floats2bfloat162_rn(v1.z, v1.w);
    __nv_bfloat162 l01 = __floats2bfloat162_rn(
        v0.x - __bfloat162float(__low2bfloat16(h01)),
        v0.y - __bfloat162float(__high2bfloat16(h01)));
    __nv_bfloat162 l23 = __floats2bfloat162_rn(
        v0.z - __bfloat162float(__low2bfloat16(h23)),
        v0.w - __bfloat162float(__high2bfloat16(h23)));
    __nv_bfloat162 l45 = __floats2bfloat162_rn(
        v1.x - __bfloat162float(__low2bfloat16(h45)),
        v1.y - __bfloat162float(__high2bfloat16(h45)));
    __nv_bfloat162 l67 = __floats2bfloat162_rn(
        v1.z - __bfloat162float(__low2bfloat16(h67)),
        v1.w - __bfloat162float(__high2bfloat16(h67)));
    hp.x = *(uint32_t*)&h01; hp.y = *(uint32_t*)&h23;
    hp.z = *(uint32_t*)&h45; hp.w = *(uint32_t*)&h67;
    lp.x = *(uint32_t*)&l01; lp.y = *(uint32_t*)&l23;
    lp.z = *(uint32_t*)&l45; lp.w = *(uint32_t*)&l67;
}

__device__ __forceinline__ void ldsm_x4(uint32_t addr, uint32_t& r0, uint32_t& r1,
                                        uint32_t& r2, uint32_t& r3) {
    asm volatile("ldmatrix.sync.aligned.m8n8.x4.shared.b16 {%0,%1,%2,%3}, [%4];"
                 : "=r"(r0), "=r"(r1), "=r"(r2), "=r"(r3) : "r"(addr));
}

__device__ __forceinline__ void mma16816(float* c, const uint32_t* a, const uint32_t* b) {
    asm volatile(
        "mma.sync.aligned.m16n8k16.row.col.f32.bf16.bf16.f32 "
        "{%0,%1,%2,%3}, {%4,%5,%6,%7}, {%8,%9}, {%0,%1,%2,%3};"
        : "+f"(c[0]), "+f"(c[1]), "+f"(c[2]), "+f"(c[3])
        : "r"(a[0]), "r"(a[1]), "r"(a[2]), "r"(a[3]), "r"(b[0]), "r"(b[1]));
}

__global__ __launch_bounds__(128, 4)
void stg_sym4_kernel(const float* __restrict__ sp, const float* __restrict__ tp,
                     float* __restrict__ out)
{
    extern __shared__ char smem[];
    const uint32_t smem_base = smem_u32(smem);

    const int t    = threadIdx.x;
    const int lane = t & 31;
    const int wid  = t >> 5;

    const int b = blockIdx.y;

    // map blockIdx.x -> (i strip of 64 rows, j strip of 128 cols), j >= floor(i/2)
    int p = blockIdx.x;
    int m = 0;
    while (m < 17 && p >= 2 * (NTJ - m)) { p -= 2 * (NTJ - m); ++m; }
    int i, j;
    if (m == 17) { i = 34; j = 17; }
    else {
        int cnt = NTJ - m;               // tiles per i at this m
        if (p >= cnt) { i = 2 * m + 1; j = m + (p - cnt); }
        else          { i = 2 * m;     j = m + p; }
    }
    const int row0 = i * TMR;
    const int col0 = j * TNC;

    // ---- load + split-convert A (64 rows) and B (128 rows) ----
    // A: 64 rows * 8 groups = 512 units / 128 thr = 4 iters
    #pragma unroll
    for (int it = 0; it < 4; ++it) {
        int idx = it * 128 + t;
        int r   = idx >> 3;
        int c8  = idx & 7;
        int g   = row0 + r;
        float4 v0 = make_float4(0.f,0.f,0.f,0.f), v1 = v0;
        if (g < MM) {
            const float* ptr = (g < NN) ? sp + ((size_t)b * NN + g) * DD
                                        : tp + ((size_t)b * TT + (g - NN)) * DD;
            v0 = ((const float4*)ptr)[c8 * 2];
            v1 = ((const float4*)ptr)[c8 * 2 + 1];
        }
        uint4 hp, lp;
        split8(v0, v1, hp, lp);
        uint32_t sw = sw128((uint32_t)r * 128 + (uint32_t)c8 * 16);
        *(uint4*)(smem + AHI_OFF + sw) = hp;
        *(uint4*)(smem + ALO_OFF + sw) = lp;
    }
    // B: 128 rows * 8 groups = 1024 units -> 8 iters
    #pragma unroll
    for (int it = 0; it < 8; ++it) {
        int idx = it * 128 + t;
        int r   = idx >> 3;
        int c8  = idx & 7;
        int g   = col0 + r;
        float4 v0 = make_float4(0.f,0.f,0.f,0.f), v1 = v0;
        if (g < MM) {
            const float* ptr = (g < NN) ? sp + ((size_t)b * NN + g) * DD
                                        : tp + ((size_t)b * TT + (g - NN)) * DD;
            v0 = ((const float4*)ptr)[c8 * 2];
            v1 = ((const float4*)ptr)[c8 * 2 + 1];
        }
        uint4 hp, lp;
        split8(v0, v1, hp, lp);
        uint32_t sw = sw128((uint32_t)r * 128 + (uint32_t)c8 * 16);
        *(uint4*)(smem + BHI_OFF + sw) = hp;
        *(uint4*)(smem + BLO_OFF + sw) = lp;
    }
    __syncthreads();

    // ---- warp tiles: 2 (m) x 2 (n) warps, each 32x64 ----
    const int m0w = (wid & 1) * 32;
    const int n0w = (wid >> 1) * 64;

    float acc[2][8][4];
    #pragma unroll
    for (int mi = 0; mi < 2; ++mi)
        #pragma unroll
        for (int ni = 0; ni < 8; ++ni)
            #pragma unroll
            for (int q = 0; q < 4; ++q) acc[mi][ni][q] = 0.0f;

    const int a_row  = m0w + (lane & 15);
    const int a_chk  = lane >> 4;
    const int b_rowb = n0w + ((lane >> 4) << 3) + (lane & 7);
    const int b_chk  = (lane >> 3) & 1;

    #pragma unroll
    for (int pass = 0; pass < 3; ++pass) {
        const uint32_t abase = smem_base + (pass == 2 ? ALO_OFF : AHI_OFF);
        const uint32_t bbase = smem_base + (pass == 1 ? BLO_OFF : BHI_OFF);
        #pragma unroll
        for (int kk = 0; kk < 4; ++kk) {
            const int kc = kk * 2;
            uint32_t af[2][4];
            #pragma unroll
            for (int mi = 0; mi < 2; ++mi) {
                uint32_t off = (uint32_t)(a_row + mi * 16) * 128 + (uint32_t)(kc + a_chk) * 16;
                ldsm_x4(abase + sw128(off), af[mi][0], af[mi][1], af[mi][2], af[mi][3]);
            }
            uint32_t bf[8][2];
            #pragma unroll
            for (int bi = 0; bi < 4; ++bi) {
                uint32_t off = (uint32_t)(b_rowb + bi * 16) * 128 + (uint32_t)(kc + b_chk) * 16;
                ldsm_x4(bbase + sw128(off), bf[2*bi][0], bf[2*bi][1], bf[2*bi+1][0], bf[2*bi+1][1]);
            }
            #pragma unroll
            for (int mi = 0; mi < 2; ++mi)
                #pragma unroll
                for (int ni = 0; ni < 8; ++ni)
                    mma16816(acc[mi][ni], af[mi], bf[ni]);
        }
    }

    // ---- activation in place ----
    #pragma unroll
    for (int mi = 0; mi < 2; ++mi)
        #pragma unroll
        for (int ni = 0; ni < 8; ++ni)
            #pragma unroll
            for (int q = 0; q < 4; ++q)
                acc[mi][ni][q] = tanh_relu(acc[mi][ni][q]);

    // ---- direct write: out[row0+r][col0+c], coalesced float2 ----
    #pragma unroll
    for (int mi = 0; mi < 2; ++mi) {
        #pragma unroll
        for (int rh = 0; rh < 2; ++rh) {
            const int gr = row0 + m0w + mi * 16 + rh * 8 + (lane >> 2);
            if (gr >= MM) continue;
            const size_t rbase = ((size_t)b * MM + gr) * MM;
            #pragma unroll
            for (int ni = 0; ni < 8; ++ni) {
                const int gc = col0 + n0w + ni * 8 + (lane & 3) * 2;
                if (gc < MM) {
                    float2 v;
                    v.x = acc[mi][ni][rh * 2];
                    v.y = acc[mi][ni][rh * 2 + 1];
                    *(float2*)&out[rbase + gc] = v;
                }
            }
        }
    }

    // ---- mirror write via SMEM transpose (always) ----
    __syncthreads();                   // done reading A/B tiles
    {
        float* Cs = (float*)smem;      // [c:128][r: pitch 68]
        #pragma unroll
        for (int mi = 0; mi < 2; ++mi) {
            #pragma unroll
            for (int rh = 0; rh < 2; ++rh) {
                const int r = m0w + mi * 16 + rh * 8 + (lane >> 2);
                #pragma unroll
                for (int ni = 0; ni < 8; ++ni) {
                    const int c = n0w + ni * 8 + (lane & 3) * 2;
                    Cs[(c)     * CS_PITCH + r] = acc[mi][ni][rh * 2];
                    Cs[(c + 1) * CS_PITCH + r] = acc[mi][ni][rh * 2 + 1];
                }
            }
        }
        __syncthreads();
        // read rows of Cs (f4), write out[col0+c][row0+r] coalesced
        // 128 cols x 16 f4-groups = 2048 f4 / 128 thr = 16 iters
        #pragma unroll
        for (int it = 0; it < 16; ++it) {
            int u   = it * 128 + t;
            int lr4 = u & 15;
            int lc  = u >> 4;
            float4 v = *(const float4*)&Cs[lc * CS_PITCH + 4 * lr4];
            int gr_out = col0 + lc;        // output row (in j strip)
            int gc_out = row0 + 4 * lr4;   // output cols (in i strip), MM%4==0
            if (gr_out < MM && gc_out + 3 < MM) {
                *(float4*)&out[((size_t)b * MM + gr_out) * MM + gc_out] = v;
            } else if (gr_out < MM) {
                float* dst = &out[((size_t)b * MM + gr_out) * MM + gc_out];
                if (gc_out     < MM) dst[0] = v.x;
                if (gc_out + 1 < MM) dst[1] = v.y;
                if (gc_out + 2 < MM) dst[2] = v.z;
                if (gc_out + 3 < MM) dst[3] = v.w;
            }
        }
    }
}

extern "C" void kernel_launch(void* const* d_in, const int* in_sizes, int n_in,
                              void* d_out, int out_size)
{
    const float* sp = (const float*)d_in[0];   // spatial  [16,2048,64] f32
    const float* tp = (const float*)d_in[1];   // temporal [16, 168,64] f32
    float* out = (float*)d_out;                // [16,2216,2216] f32

    cudaFuncSetAttribute(stg_sym4_kernel, cudaFuncAttributeMaxDynamicSharedMemorySize, SMEM_BYTES);
    dim3 grid(TILES_PER_B, BB);
    stg_sym4_kernel<<<grid, 128, SMEM_BYTES>>>(sp, tp, out);
}